// round 7
// baseline (speedup 1.0000x reference)
#include <cuda_runtime.h>
#include <math.h>
#include <stdint.h>

#define Bsz  4
#define Tlen 512
#define Edim 1024
#define Vdim 32000
#define GDIM (4*Edim)           // 4096 gate width
#define MROWS (Tlen*Bsz)        // 2048
#define NBLK 128                // persistent blocks for recurrence
#define LOGB (-1.0005003335835335e-3)    // log(1 - 0.001), double

// ---------------- scratch (static device globals; no allocation) ----------------
static __device__ __align__(16) float g_x    [MROWS * Edim];        // [T,B,E] embedded input
static __device__ __align__(16) float g_gates[MROWS * GDIM];        // [T,B,4E] ih-gates (+bias)
static __device__ __align__(16) float g_h0   [(Tlen+1) * Bsz*Edim]; // layer0 h sequence
static __device__ __align__(16) float g_h1   [(Tlen+1) * Bsz*Edim]; // layer1 h sequence

// grid-barrier state: one flag per block (no single-address atomic serialization)
static __device__ unsigned int g_flags[NBLK];

__global__ void bar_reset() { if (threadIdx.x < NBLK) g_flags[threadIdx.x] = 0; }

// ---------------- helpers ----------------
__device__ __forceinline__ float tanh_acc(float x) {   // expf-based, ~1e-7 rel err
    float ax = fabsf(x);
    float t  = expf(-2.f * ax);
    float r  = (1.f - t) / (1.f + t);
    return copysignf(r, x);
}
__device__ __forceinline__ float sigm(float x) { return 1.f / (1.f + expf(-x)); }

__device__ __forceinline__ float tf32r(float x) {      // round-to-nearest tf32
    unsigned int u;
    asm("cvt.rna.tf32.f32 %0, %1;" : "=r"(u) : "f"(x));
    return __uint_as_float(u);
}

__device__ __forceinline__ void mma_tf32(float c[4], const uint32_t a[4], const uint32_t b[2]) {
    asm volatile(
        "mma.sync.aligned.m16n8k8.row.col.f32.tf32.tf32.f32 "
        "{%0,%1,%2,%3}, {%4,%5,%6,%7}, {%8,%9}, {%0,%1,%2,%3};"
        : "+f"(c[0]), "+f"(c[1]), "+f"(c[2]), "+f"(c[3])
        : "r"(a[0]), "r"(a[1]), "r"(a[2]), "r"(a[3]), "r"(b[0]), "r"(b[1]));
}

// ---------------- embedding: x[t,b,:] = emb[tokens[b,t]] ----------------
__global__ void embed_kernel(const int* __restrict__ tokens, const float* __restrict__ emb) {
    int id = blockIdx.x * blockDim.x + threadIdx.x;
    const int EV = Edim / 4;
    if (id >= MROWS * EV) return;
    int e4 = id % EV;
    int m  = id / EV;           // m = t*B + b
    int b  = m & 3, t = m >> 2;
    int tok = tokens[b * Tlen + t];
    ((float4*)g_x)[id] = ((const float4*)(emb + (size_t)tok * Edim))[e4];
}

// ---------------- tf32 tensor-core GEMM (NT) ----------------
// C[m,n] = sum_k A[m,k]*B[n,k] + bias1[n] + bias2[n]
// BM=BN=128, BK=16. 256 threads = 8 warps in 2(m) x 4(n); warp tile 64x32.
// grid.x = M/128 (m fastest => B tiles shared across concurrent blocks via L2).
__global__ __launch_bounds__(256, 2)
void gemm_tf32_nt(const float* __restrict__ A, const float* __restrict__ B,
                  float* __restrict__ C, int M, int N, int K,
                  const float* __restrict__ bias1, const float* __restrict__ bias2,
                  int remap)
{
    __shared__ float As[128][20];   // stride 20: frag loads bank-conflict-free
    __shared__ float Bs[128][20];
    const int tid  = threadIdx.x;
    const int wid  = tid >> 5, lane = tid & 31;
    const int g    = lane >> 2, tig = lane & 3;
    const int warp_m = (wid >> 2) * 64;   // 0 / 64
    const int warp_n = (wid & 3) * 32;    // 0,32,64,96
    const int row0 = blockIdx.x * 128;
    const int col0 = blockIdx.y * 128;

    const int ldr = tid >> 2;        // 0..63
    const int ldc = (tid & 3) * 4;   // 0,4,8,12

    const float* Ap0 = A + (size_t)(row0 + ldr) * K + ldc;
    const float* Ap1 = A + (size_t)(row0 + ldr + 64) * K + ldc;
    const float* Bp0 = B + (size_t)(col0 + ldr) * K + ldc;
    const float* Bp1 = B + (size_t)(col0 + ldr + 64) * K + ldc;

    float acc[16][4];
#pragma unroll
    for (int i = 0; i < 16; i++)
#pragma unroll
        for (int j = 0; j < 4; j++) acc[i][j] = 0.f;

    float4 ra0 = *(const float4*)Ap0;
    float4 ra1 = *(const float4*)Ap1;
    float4 rb0 = *(const float4*)Bp0;
    float4 rb1 = *(const float4*)Bp1;

    for (int kb = 0; kb < K; kb += 16) {
        As[ldr     ][ldc+0] = tf32r(ra0.x); As[ldr     ][ldc+1] = tf32r(ra0.y);
        As[ldr     ][ldc+2] = tf32r(ra0.z); As[ldr     ][ldc+3] = tf32r(ra0.w);
        As[ldr + 64][ldc+0] = tf32r(ra1.x); As[ldr + 64][ldc+1] = tf32r(ra1.y);
        As[ldr + 64][ldc+2] = tf32r(ra1.z); As[ldr + 64][ldc+3] = tf32r(ra1.w);
        Bs[ldr     ][ldc+0] = tf32r(rb0.x); Bs[ldr     ][ldc+1] = tf32r(rb0.y);
        Bs[ldr     ][ldc+2] = tf32r(rb0.z); Bs[ldr     ][ldc+3] = tf32r(rb0.w);
        Bs[ldr + 64][ldc+0] = tf32r(rb1.x); Bs[ldr + 64][ldc+1] = tf32r(rb1.y);
        Bs[ldr + 64][ldc+2] = tf32r(rb1.z); Bs[ldr + 64][ldc+3] = tf32r(rb1.w);
        __syncthreads();

        if (kb + 16 < K) {               // prefetch next K-slab during compute
            ra0 = *(const float4*)(Ap0 + kb + 16);
            ra1 = *(const float4*)(Ap1 + kb + 16);
            rb0 = *(const float4*)(Bp0 + kb + 16);
            rb1 = *(const float4*)(Bp1 + kb + 16);
        }

#pragma unroll
        for (int ks = 0; ks < 2; ks++) {
            const int kc = ks * 8 + tig;
            uint32_t af[4][4], bf[4][2];
#pragma unroll
            for (int mt = 0; mt < 4; mt++) {
                int mr = warp_m + mt * 16 + g;
                af[mt][0] = __float_as_uint(As[mr    ][kc]);
                af[mt][1] = __float_as_uint(As[mr + 8][kc]);
                af[mt][2] = __float_as_uint(As[mr    ][kc + 4]);
                af[mt][3] = __float_as_uint(As[mr + 8][kc + 4]);
            }
#pragma unroll
            for (int nt = 0; nt < 4; nt++) {
                int nr = warp_n + nt * 8 + g;
                bf[nt][0] = __float_as_uint(Bs[nr][kc]);
                bf[nt][1] = __float_as_uint(Bs[nr][kc + 4]);
            }
#pragma unroll
            for (int mt = 0; mt < 4; mt++)
#pragma unroll
                for (int nt = 0; nt < 4; nt++)
                    mma_tf32(acc[mt * 4 + nt], af[mt], bf[nt]);
        }
        __syncthreads();
    }

    // epilogue
#pragma unroll
    for (int mt = 0; mt < 4; mt++) {
        int m0 = row0 + warp_m + mt * 16 + g;
        int m1 = m0 + 8;
        int r0 = remap ? ((m0 & 3) * Tlen + (m0 >> 2)) : m0;
        int r1 = remap ? ((m1 & 3) * Tlen + (m1 >> 2)) : m1;
#pragma unroll
        for (int nt = 0; nt < 4; nt++) {
            int n = col0 + warp_n + nt * 8 + tig * 2;
            float bv0 = 0.f, bv1 = 0.f;
            if (bias1) { bv0 += bias1[n]; bv1 += bias1[n + 1]; }
            if (bias2) { bv0 += bias2[n]; bv1 += bias2[n + 1]; }
            float* c = acc[mt * 4 + nt];
            float2 v0 = make_float2(c[0] + bv0, c[1] + bv1);
            float2 v1 = make_float2(c[2] + bv0, c[3] + bv1);
            *(float2*)&C[(size_t)r0 * N + n] = v0;
            *(float2*)&C[(size_t)r1 * N + n] = v1;
        }
    }
}

// ---------------- persistent LSTM layer ----------------
__global__ void __launch_bounds__(256, 1)
lstm_layer(const float* __restrict__ gih,   // [T,B,4E] input gates (bias included)
           const float* __restrict__ Whh,   // [4E,E]
           float* __restrict__ hseq)        // [T+1,B,E]; slots 1..T written
{
    extern __shared__ float sm[];
    float* ws   = sm;                  // [32][1024] weight rows (gate*8 + j)
    float* hs   = ws + 32 * 1024;      // [4][1024] h_prev
    float* garr = hs + 4 * 1024;       // [4 gates][4 b][8 j]
    float* cs   = garr + 128;          // [4 b][8 j] cell state

    const int blk  = blockIdx.x;       // 0..127
    const int e0   = blk * 8;
    const int tid  = threadIdx.x;
    const int warp = tid >> 5;
    const int lane = tid & 31;

    // load Whh slice: smem row r = g*8+j <- global row g*Edim + e0 + j
    for (int r = warp; r < 32; r += 8) {
        int g = r >> 3, j = r & 7;
        const float* src = Whh + (size_t)(g * Edim + e0 + j) * Edim;
        for (int c = lane * 4; c < Edim; c += 128)
            *(float4*)&ws[r * 1024 + c] = *(const float4*)&src[c];
    }
    if (tid < 32) cs[tid] = 0.f;
    __syncthreads();

    const int r0 = warp * 4;
    const float* wr0 = ws + (r0 + 0) * 1024;
    const float* wr1 = ws + (r0 + 1) * 1024;
    const float* wr2 = ws + (r0 + 2) * 1024;
    const float* wr3 = ws + (r0 + 3) * 1024;

    for (int t = 0; t < Tlen; t++) {
        // load h_prev
        if (t == 0) {
            for (int i = tid; i < 4096; i += 256) hs[i] = 0.f;
        } else {
            const float4* hp = (const float4*)(hseq + (size_t)t * (Bsz * Edim));
            float4* hd = (float4*)hs;
            for (int i = tid; i < 1024; i += 256) hd[i] = hp[i];
        }
        __syncthreads();

        float a00=0,a01=0,a02=0,a03=0, a10=0,a11=0,a12=0,a13=0;
        float a20=0,a21=0,a22=0,a23=0, a30=0,a31=0,a32=0,a33=0;
#pragma unroll 4
        for (int kc = lane; kc < Edim; kc += 32) {
            float h0 = hs[kc], h1 = hs[kc + 1024], h2 = hs[kc + 2048], h3 = hs[kc + 3072];
            float w0 = wr0[kc], w1 = wr1[kc], w2 = wr2[kc], w3 = wr3[kc];
            a00 = fmaf(w0, h0, a00); a01 = fmaf(w0, h1, a01); a02 = fmaf(w0, h2, a02); a03 = fmaf(w0, h3, a03);
            a10 = fmaf(w1, h0, a10); a11 = fmaf(w1, h1, a11); a12 = fmaf(w1, h2, a12); a13 = fmaf(w1, h3, a13);
            a20 = fmaf(w2, h0, a20); a21 = fmaf(w2, h1, a21); a22 = fmaf(w2, h2, a22); a23 = fmaf(w2, h3, a23);
            a30 = fmaf(w3, h0, a30); a31 = fmaf(w3, h1, a31); a32 = fmaf(w3, h2, a32); a33 = fmaf(w3, h3, a33);
        }
#pragma unroll
        for (int off = 16; off; off >>= 1) {
            a00 += __shfl_down_sync(~0u, a00, off); a01 += __shfl_down_sync(~0u, a01, off);
            a02 += __shfl_down_sync(~0u, a02, off); a03 += __shfl_down_sync(~0u, a03, off);
            a10 += __shfl_down_sync(~0u, a10, off); a11 += __shfl_down_sync(~0u, a11, off);
            a12 += __shfl_down_sync(~0u, a12, off); a13 += __shfl_down_sync(~0u, a13, off);
            a20 += __shfl_down_sync(~0u, a20, off); a21 += __shfl_down_sync(~0u, a21, off);
            a22 += __shfl_down_sync(~0u, a22, off); a23 += __shfl_down_sync(~0u, a23, off);
            a30 += __shfl_down_sync(~0u, a30, off); a31 += __shfl_down_sync(~0u, a31, off);
            a32 += __shfl_down_sync(~0u, a32, off); a33 += __shfl_down_sync(~0u, a33, off);
        }
        if (lane == 0) {
            float vals[4][4] = {{a00,a01,a02,a03},{a10,a11,a12,a13},
                                {a20,a21,a22,a23},{a30,a31,a32,a33}};
#pragma unroll
            for (int rr = 0; rr < 4; rr++) {
                int r = r0 + rr, g = r >> 3, j = r & 7;
#pragma unroll
                for (int b = 0; b < 4; b++)
                    garr[(g * 4 + b) * 8 + j] = vals[rr][b];
            }
        }
        __syncthreads();

        if (tid < 32) {
            int b = tid >> 3, j = tid & 7, e = e0 + j;
            const float* gb = gih + ((size_t)t * Bsz + b) * GDIM;
            float gi = garr[(0 * 4 + b) * 8 + j] + gb[e];
            float gf = garr[(1 * 4 + b) * 8 + j] + gb[Edim + e];
            float gG = garr[(2 * 4 + b) * 8 + j] + gb[2 * Edim + e];
            float go = garr[(3 * 4 + b) * 8 + j] + gb[3 * Edim + e];
            float c = sigm(gf) * cs[tid] + sigm(gi) * tanh_acc(gG);
            cs[tid] = c;
            hseq[(size_t)(t + 1) * (Bsz * Edim) + b * Edim + e] = sigm(go) * tanh_acc(c);
        }
        __syncthreads();   // block's h-stores complete

        // distributed flag barrier: publish own flag, spin on all 128
        unsigned int gen = (unsigned int)(t + 1);
        if (tid == 0)
            asm volatile("st.release.gpu.u32 [%0], %1;"
                         :: "l"(&g_flags[blk]), "r"(gen) : "memory");
        if (tid < NBLK) {
            unsigned int v;
            do {
                asm volatile("ld.acquire.gpu.u32 %0, [%1];"
                             : "=r"(v) : "l"(&g_flags[tid]) : "memory");
            } while (v < gen);
        }
        __syncthreads();
    }
}

// ---------------- post-processing (in place on d_out) ----------------
__global__ void postprocess(float* __restrict__ out) {
    const int r = blockIdx.x;                   // 0..2047 (row = b*T + t)
    const int t_idx = r & (Tlen - 1);
    float* z = out + (size_t)r * Vdim;
    const int VV = Vdim - 1;
    const int tid = threadIdx.x;

    __shared__ float red[256];
    __shared__ float sh_shift, sh_eos;

    float mx = -3.402823466e38f;
    for (int v = tid; v < VV; v += 256) mx = fmaxf(mx, z[v]);
    red[tid] = mx; __syncthreads();
#pragma unroll
    for (int s = 128; s; s >>= 1) { if (tid < s) red[tid] = fmaxf(red[tid], red[tid + s]); __syncthreads(); }
    mx = red[0];
    __syncthreads();

    float sum = 0.f;
    for (int v = tid; v < VV; v += 256) sum += expf(z[v] - mx);
    red[tid] = sum; __syncthreads();
#pragma unroll
    for (int s = 128; s; s >>= 1) { if (tid < s) red[tid] += red[tid + s]; __syncthreads(); }

    if (tid == 0) {
        double lse = (double)mx + log((double)red[0]);
        double e   = (double)z[VV];
        double lsn = (-e < 0 ? -e : 0.0) - log1p(exp(-fabs(e)));  // log_sigmoid(-e)
        double lsp = ( e < 0 ?  e : 0.0) - log1p(exp(-fabs(e)));  // log_sigmoid(e)
        double log_lb = (double)(t_idx + 1) * LOGB;
        double C1 = log_lb + lsn;
        double log_lb_eos = log(-expm1(log_lb)) + lsn;
        double d = log_lb_eos - lsp;
        double logsig_d = (d < 0 ? d : 0.0) - log1p(exp(-fabs(d)));
        double lpe = log_lb_eos - logsig_d;
        double m2 = fmax(C1, lpe);
        double Z  = m2 + log1p(exp(fmin(C1, lpe) - m2));
        sh_shift = (float)(C1 - lse - Z);
        sh_eos   = (float)(lpe - Z);
    }
    __syncthreads();

    float shift = sh_shift;
    for (int v = tid; v < VV; v += 256) z[v] += shift;
    if (tid == 0) z[VV] = sh_eos;
}

// ---------------- launcher ----------------
extern "C" void kernel_launch(void* const* d_in, const int* in_sizes, int n_in,
                              void* d_out, int out_size)
{
    (void)in_sizes; (void)n_in; (void)out_size;
    // metadata order = setup_inputs() dict insertion order:
    // 0:tokens 1:emb 2:Wproj 3:Wih0 4:Whh0 5:bih0 6:bhh0 7:Wih1 8:Whh1 9:bih1 10:bhh1
    const int*   tokens = (const int*)  d_in[0];
    const float* emb    = (const float*)d_in[1];
    const float* Wproj  = (const float*)d_in[2];
    const float* Wih0   = (const float*)d_in[3];
    const float* Whh0   = (const float*)d_in[4];
    const float* bih0   = (const float*)d_in[5];
    const float* bhh0   = (const float*)d_in[6];
    const float* Wih1   = (const float*)d_in[7];
    const float* Whh1   = (const float*)d_in[8];
    const float* bih1   = (const float*)d_in[9];
    const float* bhh1   = (const float*)d_in[10];
    float* out = (float*)d_out;

    float *px, *pg, *ph0, *ph1;
    cudaGetSymbolAddress((void**)&px,  g_x);
    cudaGetSymbolAddress((void**)&pg,  g_gates);
    cudaGetSymbolAddress((void**)&ph0, g_h0);
    cudaGetSymbolAddress((void**)&ph1, g_h1);

    const int lstm_smem = (32 * 1024 + 4 * 1024 + 128 + 32) * (int)sizeof(float);
    cudaFuncSetAttribute(lstm_layer, cudaFuncAttributeMaxDynamicSharedMemorySize, lstm_smem);

    // 1. embedding
    embed_kernel<<<(MROWS * Edim / 4 + 255) / 256, 256>>>(tokens, emb);

    // 2. layer-0 input gates (tf32 tensor cores)
    dim3 gg(MROWS / 128, GDIM / 128);       // (16, 32) — m fastest
    gemm_tf32_nt<<<gg, 256>>>(px, Wih0, pg, MROWS, GDIM, Edim, bih0, bhh0, 0);

    // 3. layer-0 recurrence (persistent)
    bar_reset<<<1, 128>>>();
    lstm_layer<<<NBLK, 256, lstm_smem>>>(pg, Whh0, ph0);

    // 4. layer-1 input gates
    gemm_tf32_nt<<<gg, 256>>>(ph0 + Bsz * Edim, Wih1, pg, MROWS, GDIM, Edim, bih1, bhh1, 0);

    // 5. layer-1 recurrence (persistent)
    bar_reset<<<1, 128>>>();
    lstm_layer<<<NBLK, 256, lstm_smem>>>(pg, Whh1, ph1);

    // 6. projection -> logits directly into d_out (rows remapped to [B,T] order)
    dim3 gp(MROWS / 128, Vdim / 128);       // (16, 250) — m fastest, B streams once
    gemm_tf32_nt<<<gp, 256>>>(ph1 + Bsz * Edim, Wproj, out, MROWS, Vdim, Edim,
                              nullptr, nullptr, 1);

    // 7. log-prob post-processing in place
    postprocess<<<MROWS, 256>>>(out);
}

// round 8
// speedup vs baseline: 1.8666x; 1.8666x over previous
#include <cuda_runtime.h>
#include <cuda_bf16.h>
#include <math.h>
#include <stdint.h>

#define Bsz  4
#define Tlen 512
#define Edim 1024
#define Vdim 32000
#define GDIM (4*Edim)           // 4096 gate width
#define MROWS (Tlen*Bsz)        // 2048
#define NBLK 128                // persistent blocks for recurrence
#define LOGB (-1.0005003335835335e-3)    // log(1 - 0.001), double

// ---------------- scratch (static device globals; no allocation) ----------------
static __device__ __align__(16) __nv_bfloat16 g_xbf [MROWS * Edim];       // embedded input, bf16
static __device__ __align__(16) float g_gates[MROWS * GDIM];              // ih-gates (+bias), fp32
static __device__ __align__(16) float g_h0   [(Tlen+1) * Bsz*Edim];       // layer0 h (fp32)
static __device__ __align__(16) float g_h1   [(Tlen+1) * Bsz*Edim];       // layer1 h (fp32)
static __device__ __align__(16) __nv_bfloat16 g_h0bf[(Tlen+1) * Bsz*Edim];
static __device__ __align__(16) __nv_bfloat16 g_h1bf[(Tlen+1) * Bsz*Edim];
static __device__ __align__(16) __nv_bfloat16 g_wih0bf[GDIM * Edim];
static __device__ __align__(16) __nv_bfloat16 g_wih1bf[GDIM * Edim];
static __device__ __align__(16) __nv_bfloat16 g_wprojbf[(size_t)Vdim * Edim];

// grid-barrier state (round-6 proven version)
static __device__ unsigned int g_arrive;
static __device__ unsigned int g_release;
__global__ void bar_reset() { g_arrive = 0; g_release = 0; }

// ---------------- helpers ----------------
__device__ __forceinline__ float tanh_acc(float x) {
    float ax = fabsf(x);
    float t  = expf(-2.f * ax);
    float r  = (1.f - t) / (1.f + t);
    return copysignf(r, x);
}
__device__ __forceinline__ float sigm(float x) { return 1.f / (1.f + expf(-x)); }

__device__ __forceinline__ void grid_barrier_t0(unsigned int gen) {
    __threadfence();
    unsigned int prev = atomicAdd(&g_arrive, 1u);
    if (prev + 1u == gen * NBLK) {
        __threadfence();
        asm volatile("st.release.gpu.u32 [%0], %1;"
                     :: "l"(&g_release), "r"(gen) : "memory");
    } else {
        unsigned int v;
        do {
            asm volatile("ld.acquire.gpu.u32 %0, [%1];"
                         : "=r"(v) : "l"(&g_release) : "memory");
        } while (v < gen);
    }
}

__device__ __forceinline__ void ldsm_x4(uint32_t& r0, uint32_t& r1, uint32_t& r2, uint32_t& r3,
                                        uint32_t addr) {
    asm volatile("ldmatrix.sync.aligned.m8n8.x4.shared.b16 {%0,%1,%2,%3}, [%4];"
                 : "=r"(r0), "=r"(r1), "=r"(r2), "=r"(r3) : "r"(addr));
}
__device__ __forceinline__ void mma_bf16(float c[4], const uint32_t a[4], const uint32_t b[2]) {
    asm volatile(
        "mma.sync.aligned.m16n8k16.row.col.f32.bf16.bf16.f32 "
        "{%0,%1,%2,%3}, {%4,%5,%6,%7}, {%8,%9}, {%0,%1,%2,%3};"
        : "+f"(c[0]), "+f"(c[1]), "+f"(c[2]), "+f"(c[3])
        : "r"(a[0]), "r"(a[1]), "r"(a[2]), "r"(a[3]), "r"(b[0]), "r"(b[1]));
}

// ---------------- fp32 -> bf16 conversion ----------------
__global__ void f2bf_kernel(const float* __restrict__ s, __nv_bfloat16* __restrict__ d, int n) {
    int idx = (blockIdx.x * blockDim.x + threadIdx.x) * 4;
    if (idx >= n) return;
    float4 v = *(const float4*)(s + idx);
    __nv_bfloat162 lo = __floats2bfloat162_rn(v.x, v.y);
    __nv_bfloat162 hi = __floats2bfloat162_rn(v.z, v.w);
    uint2 p;
    p.x = *(uint32_t*)&lo; p.y = *(uint32_t*)&hi;
    *(uint2*)(d + idx) = p;
}

// ---------------- embedding -> bf16: x[t,b,:] = emb[tokens[b,t]] ----------------
__global__ void embed_kernel(const int* __restrict__ tokens, const float* __restrict__ emb) {
    int id = blockIdx.x * blockDim.x + threadIdx.x;
    const int EV = Edim / 4;
    if (id >= MROWS * EV) return;
    int e4 = id % EV;
    int m  = id / EV;           // m = t*B + b
    int b  = m & 3, t = m >> 2;
    int tok = tokens[b * Tlen + t];
    float4 v = ((const float4*)(emb + (size_t)tok * Edim))[e4];
    __nv_bfloat162 lo = __floats2bfloat162_rn(v.x, v.y);
    __nv_bfloat162 hi = __floats2bfloat162_rn(v.z, v.w);
    uint2 p; p.x = *(uint32_t*)&lo; p.y = *(uint32_t*)&hi;
    *(uint2*)(g_xbf + (size_t)id * 4) = p;
}

// ---------------- bf16 tensor-core GEMM (NT) ----------------
// C[m,n] = sum_k A[m,k]*B[n,k] + bias1[n] + bias2[n]; A,B bf16, C fp32.
// BM=BN=128, BK=32. 8 warps 2(m)x4(n), warp tile 64x32, mma m16n8k16.
// SMEM row stride 40 bf16 (80B): ldmatrix rows hit disjoint bank groups.
__global__ __launch_bounds__(256)
void gemm_bf16_nt(const __nv_bfloat16* __restrict__ A, const __nv_bfloat16* __restrict__ B,
                  float* __restrict__ C, int M, int N, int K,
                  const float* __restrict__ bias1, const float* __restrict__ bias2,
                  int remap)
{
    __shared__ __align__(16) __nv_bfloat16 As[128 * 40];
    __shared__ __align__(16) __nv_bfloat16 Bs[128 * 40];
    const int tid  = threadIdx.x;
    const int wid  = tid >> 5, lane = tid & 31;
    const int g    = lane >> 2, tig = lane & 3;
    const int q    = lane >> 3, r = lane & 7;
    const int warp_m = (wid >> 2) * 64;
    const int warp_n = (wid & 3) * 32;
    const int row0 = blockIdx.x * 128;
    const int col0 = blockIdx.y * 128;

    // loaders: 16B (8 bf16) per thread, 2 row-slabs per operand
    const int ldr = tid >> 2;        // 0..63
    const int ldc = (tid & 3) * 8;   // bf16 col 0,8,16,24

    const __nv_bfloat16* Ap0 = A + (size_t)(row0 + ldr) * K + ldc;
    const __nv_bfloat16* Ap1 = A + (size_t)(row0 + ldr + 64) * K + ldc;
    const __nv_bfloat16* Bp0 = B + (size_t)(col0 + ldr) * K + ldc;
    const __nv_bfloat16* Bp1 = B + (size_t)(col0 + ldr + 64) * K + ldc;

    const uint32_t as_base = (uint32_t)__cvta_generic_to_shared(As);
    const uint32_t bs_base = (uint32_t)__cvta_generic_to_shared(Bs);
    const uint32_t a_addr0 = as_base + (uint32_t)(((warp_m + (q & 1) * 8 + r) * 40 + (q >> 1) * 8) * 2);
    const uint32_t b_addr0 = bs_base + (uint32_t)(((warp_n + (q & 1) * 8 + r) * 40 + (q >> 1) * 8) * 2);

    float acc[16][4];
#pragma unroll
    for (int i = 0; i < 16; i++)
#pragma unroll
        for (int j = 0; j < 4; j++) acc[i][j] = 0.f;

    uint4 pa0 = *(const uint4*)Ap0;
    uint4 pa1 = *(const uint4*)Ap1;
    uint4 pb0 = *(const uint4*)Bp0;
    uint4 pb1 = *(const uint4*)Bp1;

    for (int kb = 0; kb < K; kb += 32) {
        *(uint4*)&As[ldr * 40 + ldc]        = pa0;
        *(uint4*)&As[(ldr + 64) * 40 + ldc] = pa1;
        *(uint4*)&Bs[ldr * 40 + ldc]        = pb0;
        *(uint4*)&Bs[(ldr + 64) * 40 + ldc] = pb1;
        __syncthreads();

        if (kb + 32 < K) {
            pa0 = *(const uint4*)(Ap0 + kb + 32);
            pa1 = *(const uint4*)(Ap1 + kb + 32);
            pb0 = *(const uint4*)(Bp0 + kb + 32);
            pb1 = *(const uint4*)(Bp1 + kb + 32);
        }

#pragma unroll
        for (int ks = 0; ks < 2; ks++) {
            uint32_t af[4][4], bf[4][2];
#pragma unroll
            for (int mt = 0; mt < 4; mt++)
                ldsm_x4(af[mt][0], af[mt][1], af[mt][2], af[mt][3],
                        a_addr0 + (uint32_t)((mt * 16 * 40 + ks * 16) * 2));
#pragma unroll
            for (int bt = 0; bt < 2; bt++) {
                uint32_t m0, m1, m2, m3;
                ldsm_x4(m0, m1, m2, m3,
                        b_addr0 + (uint32_t)((bt * 16 * 40 + ks * 16) * 2));
                bf[bt * 2 + 0][0] = m0; bf[bt * 2 + 1][0] = m1;
                bf[bt * 2 + 0][1] = m2; bf[bt * 2 + 1][1] = m3;
            }
#pragma unroll
            for (int mt = 0; mt < 4; mt++)
#pragma unroll
                for (int nt = 0; nt < 4; nt++)
                    mma_bf16(acc[mt * 4 + nt], af[mt], bf[nt]);
        }
        __syncthreads();
    }

    // epilogue
#pragma unroll
    for (int mt = 0; mt < 4; mt++) {
        int m0 = row0 + warp_m + mt * 16 + g;
        int m1 = m0 + 8;
        int r0 = remap ? ((m0 & 3) * Tlen + (m0 >> 2)) : m0;
        int r1 = remap ? ((m1 & 3) * Tlen + (m1 >> 2)) : m1;
#pragma unroll
        for (int nt = 0; nt < 4; nt++) {
            int n = col0 + warp_n + nt * 8 + tig * 2;
            float bv0 = 0.f, bv1 = 0.f;
            if (bias1) { bv0 += bias1[n]; bv1 += bias1[n + 1]; }
            if (bias2) { bv0 += bias2[n]; bv1 += bias2[n + 1]; }
            float* c = acc[mt * 4 + nt];
            *(float2*)&C[(size_t)r0 * N + n] = make_float2(c[0] + bv0, c[1] + bv1);
            *(float2*)&C[(size_t)r1 * N + n] = make_float2(c[2] + bv0, c[3] + bv1);
        }
    }
}

// ---------------- persistent LSTM layer ----------------
__global__ void __launch_bounds__(256, 1)
lstm_layer(const float* __restrict__ gih,   // [T,B,4E] input gates (bias included)
           const float* __restrict__ Whh,   // [4E,E]
           float* __restrict__ hseq,        // [T+1,B,E] fp32
           __nv_bfloat16* __restrict__ hbf) // [T+1,B,E] bf16 copy for GEMMs
{
    extern __shared__ float sm[];
    float* ws   = sm;                  // [32][1024]
    float* hs   = ws + 32 * 1024;      // [4][1024]
    float* garr = hs + 4 * 1024;       // [4 gates][4 b][8 j]
    float* cs   = garr + 128;          // [4 b][8 j]

    const int blk  = blockIdx.x;
    const int e0   = blk * 8;
    const int tid  = threadIdx.x;
    const int warp = tid >> 5;
    const int lane = tid & 31;

    for (int r = warp; r < 32; r += 8) {
        int g = r >> 3, j = r & 7;
        const float* src = Whh + (size_t)(g * Edim + e0 + j) * Edim;
        for (int c = lane * 4; c < Edim; c += 128)
            *(float4*)&ws[r * 1024 + c] = *(const float4*)&src[c];
    }
    if (tid < 32) cs[tid] = 0.f;
    __syncthreads();

    const int r0 = warp * 4;
    const float* wr0 = ws + (r0 + 0) * 1024;
    const float* wr1 = ws + (r0 + 1) * 1024;
    const float* wr2 = ws + (r0 + 2) * 1024;
    const float* wr3 = ws + (r0 + 3) * 1024;

    for (int t = 0; t < Tlen; t++) {
        if (t == 0) {
            for (int i = tid; i < 4096; i += 256) hs[i] = 0.f;
        } else {
            const float4* hp = (const float4*)(hseq + (size_t)t * (Bsz * Edim));
            float4* hd = (float4*)hs;
            for (int i = tid; i < 1024; i += 256) hd[i] = hp[i];
        }
        __syncthreads();

        float a00=0,a01=0,a02=0,a03=0, a10=0,a11=0,a12=0,a13=0;
        float a20=0,a21=0,a22=0,a23=0, a30=0,a31=0,a32=0,a33=0;
#pragma unroll 4
        for (int kc = lane; kc < Edim; kc += 32) {
            float h0 = hs[kc], h1 = hs[kc + 1024], h2 = hs[kc + 2048], h3 = hs[kc + 3072];
            float w0 = wr0[kc], w1 = wr1[kc], w2 = wr2[kc], w3 = wr3[kc];
            a00 = fmaf(w0, h0, a00); a01 = fmaf(w0, h1, a01); a02 = fmaf(w0, h2, a02); a03 = fmaf(w0, h3, a03);
            a10 = fmaf(w1, h0, a10); a11 = fmaf(w1, h1, a11); a12 = fmaf(w1, h2, a12); a13 = fmaf(w1, h3, a13);
            a20 = fmaf(w2, h0, a20); a21 = fmaf(w2, h1, a21); a22 = fmaf(w2, h2, a22); a23 = fmaf(w2, h3, a23);
            a30 = fmaf(w3, h0, a30); a31 = fmaf(w3, h1, a31); a32 = fmaf(w3, h2, a32); a33 = fmaf(w3, h3, a33);
        }
#pragma unroll
        for (int off = 16; off; off >>= 1) {
            a00 += __shfl_down_sync(~0u, a00, off); a01 += __shfl_down_sync(~0u, a01, off);
            a02 += __shfl_down_sync(~0u, a02, off); a03 += __shfl_down_sync(~0u, a03, off);
            a10 += __shfl_down_sync(~0u, a10, off); a11 += __shfl_down_sync(~0u, a11, off);
            a12 += __shfl_down_sync(~0u, a12, off); a13 += __shfl_down_sync(~0u, a13, off);
            a20 += __shfl_down_sync(~0u, a20, off); a21 += __shfl_down_sync(~0u, a21, off);
            a22 += __shfl_down_sync(~0u, a22, off); a23 += __shfl_down_sync(~0u, a23, off);
            a30 += __shfl_down_sync(~0u, a30, off); a31 += __shfl_down_sync(~0u, a31, off);
            a32 += __shfl_down_sync(~0u, a32, off); a33 += __shfl_down_sync(~0u, a33, off);
        }
        if (lane == 0) {
            float vals[4][4] = {{a00,a01,a02,a03},{a10,a11,a12,a13},
                                {a20,a21,a22,a23},{a30,a31,a32,a33}};
#pragma unroll
            for (int rr = 0; rr < 4; rr++) {
                int r = r0 + rr, g = r >> 3, j = r & 7;
#pragma unroll
                for (int b = 0; b < 4; b++)
                    garr[(g * 4 + b) * 8 + j] = vals[rr][b];
            }
        }
        __syncthreads();

        if (tid < 32) {
            int b = tid >> 3, j = tid & 7, e = e0 + j;
            const float* gb = gih + ((size_t)t * Bsz + b) * GDIM;
            float gi = garr[(0 * 4 + b) * 8 + j] + gb[e];
            float gf = garr[(1 * 4 + b) * 8 + j] + gb[Edim + e];
            float gG = garr[(2 * 4 + b) * 8 + j] + gb[2 * Edim + e];
            float go = garr[(3 * 4 + b) * 8 + j] + gb[3 * Edim + e];
            float c = sigm(gf) * cs[tid] + sigm(gi) * tanh_acc(gG);
            cs[tid] = c;
            float hv = sigm(go) * tanh_acc(c);
            size_t oi = (size_t)(t + 1) * (Bsz * Edim) + b * Edim + e;
            hseq[oi] = hv;
            hbf[oi]  = __float2bfloat16(hv);
        }
        __syncthreads();

        if (tid == 0) grid_barrier_t0((unsigned int)(t + 1));
        __syncthreads();
    }
}

// ---------------- post-processing (in place on d_out) ----------------
__global__ void postprocess(float* __restrict__ out) {
    const int r = blockIdx.x;
    const int t_idx = r & (Tlen - 1);
    float* z = out + (size_t)r * Vdim;
    const int VV = Vdim - 1;
    const int tid = threadIdx.x;

    __shared__ float red[256];
    __shared__ float sh_shift, sh_eos;

    float mx = -3.402823466e38f;
    for (int v = tid; v < VV; v += 256) mx = fmaxf(mx, z[v]);
    red[tid] = mx; __syncthreads();
#pragma unroll
    for (int s = 128; s; s >>= 1) { if (tid < s) red[tid] = fmaxf(red[tid], red[tid + s]); __syncthreads(); }
    mx = red[0];
    __syncthreads();

    float sum = 0.f;
    for (int v = tid; v < VV; v += 256) sum += expf(z[v] - mx);
    red[tid] = sum; __syncthreads();
#pragma unroll
    for (int s = 128; s; s >>= 1) { if (tid < s) red[tid] += red[tid + s]; __syncthreads(); }

    if (tid == 0) {
        double lse = (double)mx + log((double)red[0]);
        double e   = (double)z[VV];
        double lsn = (-e < 0 ? -e : 0.0) - log1p(exp(-fabs(e)));
        double lsp = ( e < 0 ?  e : 0.0) - log1p(exp(-fabs(e)));
        double log_lb = (double)(t_idx + 1) * LOGB;
        double C1 = log_lb + lsn;
        double log_lb_eos = log(-expm1(log_lb)) + lsn;
        double d = log_lb_eos - lsp;
        double logsig_d = (d < 0 ? d : 0.0) - log1p(exp(-fabs(d)));
        double lpe = log_lb_eos - logsig_d;
        double m2 = fmax(C1, lpe);
        double Z  = m2 + log1p(exp(fmin(C1, lpe) - m2));
        sh_shift = (float)(C1 - lse - Z);
        sh_eos   = (float)(lpe - Z);
    }
    __syncthreads();

    float shift = sh_shift;
    for (int v = tid; v < VV; v += 256) z[v] += shift;
    if (tid == 0) z[VV] = sh_eos;
}

// ---------------- launcher ----------------
extern "C" void kernel_launch(void* const* d_in, const int* in_sizes, int n_in,
                              void* d_out, int out_size)
{
    (void)in_sizes; (void)n_in; (void)out_size;
    // 0:tokens 1:emb 2:Wproj 3:Wih0 4:Whh0 5:bih0 6:bhh0 7:Wih1 8:Whh1 9:bih1 10:bhh1
    const int*   tokens = (const int*)  d_in[0];
    const float* emb    = (const float*)d_in[1];
    const float* Wproj  = (const float*)d_in[2];
    const float* Wih0   = (const float*)d_in[3];
    const float* Whh0   = (const float*)d_in[4];
    const float* bih0   = (const float*)d_in[5];
    const float* bhh0   = (const float*)d_in[6];
    const float* Wih1   = (const float*)d_in[7];
    const float* Whh1   = (const float*)d_in[8];
    const float* bih1   = (const float*)d_in[9];
    const float* bhh1   = (const float*)d_in[10];
    float* out = (float*)d_out;

    __nv_bfloat16 *pxbf, *ph0bf, *ph1bf, *pw0, *pw1, *pwp;
    float *pg, *ph0, *ph1;
    cudaGetSymbolAddress((void**)&pxbf,  g_xbf);
    cudaGetSymbolAddress((void**)&pg,    g_gates);
    cudaGetSymbolAddress((void**)&ph0,   g_h0);
    cudaGetSymbolAddress((void**)&ph1,   g_h1);
    cudaGetSymbolAddress((void**)&ph0bf, g_h0bf);
    cudaGetSymbolAddress((void**)&ph1bf, g_h1bf);
    cudaGetSymbolAddress((void**)&pw0,   g_wih0bf);
    cudaGetSymbolAddress((void**)&pw1,   g_wih1bf);
    cudaGetSymbolAddress((void**)&pwp,   g_wprojbf);

    const int lstm_smem = (32 * 1024 + 4 * 1024 + 128 + 32) * (int)sizeof(float);
    cudaFuncSetAttribute(lstm_layer, cudaFuncAttributeMaxDynamicSharedMemorySize, lstm_smem);

    // 0. weight conversions (fp32 -> bf16)
    f2bf_kernel<<<GDIM * Edim / 1024, 256>>>(Wih0, pw0, GDIM * Edim);
    f2bf_kernel<<<GDIM * Edim / 1024, 256>>>(Wih1, pw1, GDIM * Edim);
    f2bf_kernel<<<Vdim * (Edim / 1024), 256>>>(Wproj, pwp, Vdim * Edim);

    // 1. embedding (bf16 out)
    embed_kernel<<<(MROWS * Edim / 4 + 255) / 256, 256>>>(tokens, emb);

    // 2. layer-0 input gates (bf16 tensor cores)
    dim3 gg(MROWS / 128, GDIM / 128);       // m fastest
    gemm_bf16_nt<<<gg, 256>>>(pxbf, pw0, pg, MROWS, GDIM, Edim, bih0, bhh0, 0);

    // 3. layer-0 recurrence
    bar_reset<<<1, 1>>>();
    lstm_layer<<<NBLK, 256, lstm_smem>>>(pg, Whh0, ph0, ph0bf);

    // 4. layer-1 input gates
    gemm_bf16_nt<<<gg, 256>>>(ph0bf + Bsz * Edim, pw1, pg, MROWS, GDIM, Edim, bih1, bhh1, 0);

    // 5. layer-1 recurrence
    bar_reset<<<1, 1>>>();
    lstm_layer<<<NBLK, 256, lstm_smem>>>(pg, Whh1, ph1, ph1bf);

    // 6. projection -> d_out (rows remapped to [B,T])
    dim3 gp(MROWS / 128, Vdim / 128);       // (16, 250)
    gemm_bf16_nt<<<gp, 256>>>(ph1bf + Bsz * Edim, pwp, out, MROWS, Vdim, Edim,
                              nullptr, nullptr, 1);

    // 7. post-processing
    postprocess<<<MROWS, 256>>>(out);
}

// round 9
// speedup vs baseline: 2.0796x; 1.1141x over previous
#include <cuda_runtime.h>
#include <cuda_bf16.h>
#include <math.h>
#include <stdint.h>

#define Bsz  4
#define Tlen 512
#define Edim 1024
#define Vdim 32000
#define GDIM (4*Edim)           // 4096 gate width
#define MROWS (Tlen*Bsz)        // 2048
#define NBLK 128                // persistent blocks for recurrence
#define LOGB (-1.0005003335835335e-3)    // log(1 - 0.001), double

// ---------------- scratch (static device globals; no allocation) ----------------
static __device__ __align__(16) __nv_bfloat16 g_xbf [MROWS * Edim];       // embedded input, bf16
static __device__ __align__(16) float g_gates[MROWS * GDIM];              // ih-gates (+bias), fp32
static __device__ __align__(16) __nv_bfloat16 g_h0bf[(Tlen+1) * Bsz*Edim];
static __device__ __align__(16) __nv_bfloat16 g_h1bf[(Tlen+1) * Bsz*Edim];
static __device__ __align__(16) __nv_bfloat16 g_wih0bf[GDIM * Edim];
static __device__ __align__(16) __nv_bfloat16 g_wih1bf[GDIM * Edim];
static __device__ __align__(16) __nv_bfloat16 g_wprojbf[(size_t)Vdim * Edim];

// grid-barrier state (proven round-6 version)
static __device__ unsigned int g_arrive;
static __device__ unsigned int g_release;
__global__ void bar_reset() { g_arrive = 0; g_release = 0; }

// ---------------- helpers ----------------
__device__ __forceinline__ float tanh_acc(float x) {
    float ax = fabsf(x);
    float t  = expf(-2.f * ax);
    float r  = (1.f - t) / (1.f + t);
    return copysignf(r, x);
}
__device__ __forceinline__ float sigm(float x) { return 1.f / (1.f + expf(-x)); }

__device__ __forceinline__ void grid_barrier_t0(unsigned int gen) {
    __threadfence();
    unsigned int prev = atomicAdd(&g_arrive, 1u);
    if (prev + 1u == gen * NBLK) {
        __threadfence();
        asm volatile("st.release.gpu.u32 [%0], %1;"
                     :: "l"(&g_release), "r"(gen) : "memory");
    } else {
        unsigned int v;
        do {
            asm volatile("ld.acquire.gpu.u32 %0, [%1];"
                         : "=r"(v) : "l"(&g_release) : "memory");
        } while (v < gen);
    }
}

// bf16x2 (packed u32) -> f32x2 (packed u64)
__device__ __forceinline__ unsigned long long bf2f2(uint32_t p) {
    uint32_t lo = p << 16;
    uint32_t hi = p & 0xFFFF0000u;
    unsigned long long r;
    asm("mov.b64 %0, {%1,%2};" : "=l"(r) : "r"(lo), "r"(hi));
    return r;
}
__device__ __forceinline__ void fma2(unsigned long long& acc,
                                     unsigned long long a, unsigned long long b) {
    asm("fma.rn.f32x2 %0, %1, %2, %0;" : "+l"(acc) : "l"(a), "l"(b));
}
__device__ __forceinline__ float f2sum(unsigned long long acc) {
    uint32_t lo, hi;
    asm("mov.b64 {%0,%1}, %2;" : "=r"(lo), "=r"(hi) : "l"(acc));
    return __uint_as_float(lo) + __uint_as_float(hi);
}
__device__ __forceinline__ uint32_t packbf(float a, float b) {
    __nv_bfloat162 t = __floats2bfloat162_rn(a, b);
    return *(uint32_t*)&t;
}

__device__ __forceinline__ void ldsm_x4(uint32_t& r0, uint32_t& r1, uint32_t& r2, uint32_t& r3,
                                        uint32_t addr) {
    asm volatile("ldmatrix.sync.aligned.m8n8.x4.shared.b16 {%0,%1,%2,%3}, [%4];"
                 : "=r"(r0), "=r"(r1), "=r"(r2), "=r"(r3) : "r"(addr));
}
__device__ __forceinline__ void mma_bf16(float c[4], const uint32_t a[4], const uint32_t b[2]) {
    asm volatile(
        "mma.sync.aligned.m16n8k16.row.col.f32.bf16.bf16.f32 "
        "{%0,%1,%2,%3}, {%4,%5,%6,%7}, {%8,%9}, {%0,%1,%2,%3};"
        : "+f"(c[0]), "+f"(c[1]), "+f"(c[2]), "+f"(c[3])
        : "r"(a[0]), "r"(a[1]), "r"(a[2]), "r"(a[3]), "r"(b[0]), "r"(b[1]));
}

// ---------------- fp32 -> bf16 conversion ----------------
__global__ void f2bf_kernel(const float* __restrict__ s, __nv_bfloat16* __restrict__ d, int n) {
    int idx = (blockIdx.x * blockDim.x + threadIdx.x) * 4;
    if (idx >= n) return;
    float4 v = *(const float4*)(s + idx);
    uint2 p;
    p.x = packbf(v.x, v.y); p.y = packbf(v.z, v.w);
    *(uint2*)(d + idx) = p;
}

// ---------------- embedding -> bf16: x[t,b,:] = emb[tokens[b,t]] ----------------
__global__ void embed_kernel(const int* __restrict__ tokens, const float* __restrict__ emb) {
    int id = blockIdx.x * blockDim.x + threadIdx.x;
    const int EV = Edim / 4;
    if (id >= MROWS * EV) return;
    int e4 = id % EV;
    int m  = id / EV;           // m = t*B + b
    int b  = m & 3, t = m >> 2;
    int tok = tokens[b * Tlen + t];
    float4 v = ((const float4*)(emb + (size_t)tok * Edim))[e4];
    uint2 p; p.x = packbf(v.x, v.y); p.y = packbf(v.z, v.w);
    *(uint2*)(g_xbf + (size_t)id * 4) = p;
}

// ---------------- bf16 tensor-core GEMM (NT) — unchanged from round 8 ----------------
__global__ __launch_bounds__(256)
void gemm_bf16_nt(const __nv_bfloat16* __restrict__ A, const __nv_bfloat16* __restrict__ B,
                  float* __restrict__ C, int M, int N, int K,
                  const float* __restrict__ bias1, const float* __restrict__ bias2,
                  int remap)
{
    __shared__ __align__(16) __nv_bfloat16 As[128 * 40];
    __shared__ __align__(16) __nv_bfloat16 Bs[128 * 40];
    const int tid  = threadIdx.x;
    const int wid  = tid >> 5, lane = tid & 31;
    const int g    = lane >> 2, tig = lane & 3;
    const int q    = lane >> 3, r = lane & 7;
    const int warp_m = (wid >> 2) * 64;
    const int warp_n = (wid & 3) * 32;
    const int row0 = blockIdx.x * 128;
    const int col0 = blockIdx.y * 128;

    const int ldr = tid >> 2;
    const int ldc = (tid & 3) * 8;

    const __nv_bfloat16* Ap0 = A + (size_t)(row0 + ldr) * K + ldc;
    const __nv_bfloat16* Ap1 = A + (size_t)(row0 + ldr + 64) * K + ldc;
    const __nv_bfloat16* Bp0 = B + (size_t)(col0 + ldr) * K + ldc;
    const __nv_bfloat16* Bp1 = B + (size_t)(col0 + ldr + 64) * K + ldc;

    const uint32_t as_base = (uint32_t)__cvta_generic_to_shared(As);
    const uint32_t bs_base = (uint32_t)__cvta_generic_to_shared(Bs);
    const uint32_t a_addr0 = as_base + (uint32_t)(((warp_m + (q & 1) * 8 + r) * 40 + (q >> 1) * 8) * 2);
    const uint32_t b_addr0 = bs_base + (uint32_t)(((warp_n + (q & 1) * 8 + r) * 40 + (q >> 1) * 8) * 2);

    float acc[16][4];
#pragma unroll
    for (int i = 0; i < 16; i++)
#pragma unroll
        for (int j = 0; j < 4; j++) acc[i][j] = 0.f;

    uint4 pa0 = *(const uint4*)Ap0;
    uint4 pa1 = *(const uint4*)Ap1;
    uint4 pb0 = *(const uint4*)Bp0;
    uint4 pb1 = *(const uint4*)Bp1;

    for (int kb = 0; kb < K; kb += 32) {
        *(uint4*)&As[ldr * 40 + ldc]        = pa0;
        *(uint4*)&As[(ldr + 64) * 40 + ldc] = pa1;
        *(uint4*)&Bs[ldr * 40 + ldc]        = pb0;
        *(uint4*)&Bs[(ldr + 64) * 40 + ldc] = pb1;
        __syncthreads();

        if (kb + 32 < K) {
            pa0 = *(const uint4*)(Ap0 + kb + 32);
            pa1 = *(const uint4*)(Ap1 + kb + 32);
            pb0 = *(const uint4*)(Bp0 + kb + 32);
            pb1 = *(const uint4*)(Bp1 + kb + 32);
        }

#pragma unroll
        for (int ks = 0; ks < 2; ks++) {
            uint32_t af[4][4], bf[4][2];
#pragma unroll
            for (int mt = 0; mt < 4; mt++)
                ldsm_x4(af[mt][0], af[mt][1], af[mt][2], af[mt][3],
                        a_addr0 + (uint32_t)((mt * 16 * 40 + ks * 16) * 2));
#pragma unroll
            for (int bt = 0; bt < 2; bt++) {
                uint32_t m0, m1, m2, m3;
                ldsm_x4(m0, m1, m2, m3,
                        b_addr0 + (uint32_t)((bt * 16 * 40 + ks * 16) * 2));
                bf[bt * 2 + 0][0] = m0; bf[bt * 2 + 1][0] = m1;
                bf[bt * 2 + 0][1] = m2; bf[bt * 2 + 1][1] = m3;
            }
#pragma unroll
            for (int mt = 0; mt < 4; mt++)
#pragma unroll
                for (int nt = 0; nt < 4; nt++)
                    mma_bf16(acc[mt * 4 + nt], af[mt], bf[nt]);
        }
        __syncthreads();
    }

#pragma unroll
    for (int mt = 0; mt < 4; mt++) {
        int m0 = row0 + warp_m + mt * 16 + g;
        int m1 = m0 + 8;
        int r0 = remap ? ((m0 & 3) * Tlen + (m0 >> 2)) : m0;
        int r1 = remap ? ((m1 & 3) * Tlen + (m1 >> 2)) : m1;
#pragma unroll
        for (int nt = 0; nt < 4; nt++) {
            int n = col0 + warp_n + nt * 8 + tig * 2;
            float bv0 = 0.f, bv1 = 0.f;
            if (bias1) { bv0 += bias1[n]; bv1 += bias1[n + 1]; }
            if (bias2) { bv0 += bias2[n]; bv1 += bias2[n + 1]; }
            float* c = acc[mt * 4 + nt];
            *(float2*)&C[(size_t)r0 * N + n] = make_float2(c[0] + bv0, c[1] + bv1);
            *(float2*)&C[(size_t)r1 * N + n] = make_float2(c[2] + bv0, c[3] + bv1);
        }
    }
}

// ---------------- persistent LSTM layer (bf16 weights/h, f32x2 packed FMA) ----------------
// SMEM: wsb [32 rows][512] u32 (bf16x2, k-pairs)  64KB
//       hsb [4 b][512]     u32 (bf16x2)            8KB
//       garr [4g][4b][8j] fp32, cs [4b][8j] fp32
__global__ void __launch_bounds__(256, 1)
lstm_layer(const float* __restrict__ gih,          // [T,B,4E] fp32 gates (+bias)
           const float* __restrict__ Whh,          // [4E,E] fp32
           __nv_bfloat16* __restrict__ hbf)        // [T+1,B,E] bf16; slots 1..T written
{
    extern __shared__ uint32_t smu[];
    uint32_t* wsb = smu;                    // 32*512
    uint32_t* hsb = wsb + 32 * 512;         // 4*512
    float*    garr = (float*)(hsb + 4 * 512);  // 128
    float*    cs   = garr + 128;               // 32

    const int blk  = blockIdx.x;
    const int e0   = blk * 8;
    const int tid  = threadIdx.x;
    const int warp = tid >> 5;
    const int lane = tid & 31;

    // load + convert Whh slice to bf16 pairs
    for (int r = warp; r < 32; r += 8) {
        int g = r >> 3, j = r & 7;
        const float* src = Whh + (size_t)(g * Edim + e0 + j) * Edim;
        for (int c = lane * 4; c < Edim; c += 128) {
            float4 v = *(const float4*)&src[c];
            wsb[r * 512 + (c >> 1)]     = packbf(v.x, v.y);
            wsb[r * 512 + (c >> 1) + 1] = packbf(v.z, v.w);
        }
    }
    if (tid < 32) cs[tid] = 0.f;
    __syncthreads();

    const int r0 = warp * 4;
    const uint32_t* wp0 = wsb + (r0 + 0) * 512;
    const uint32_t* wp1 = wsb + (r0 + 1) * 512;
    const uint32_t* wp2 = wsb + (r0 + 2) * 512;
    const uint32_t* wp3 = wsb + (r0 + 3) * 512;

    for (int t = 0; t < Tlen; t++) {
        // stage h_prev (bf16) into smem
        if (t == 0) {
            for (int i = tid; i < 2048; i += 256) hsb[i] = 0u;
        } else {
            const uint4* hp = (const uint4*)(hbf + (size_t)t * (Bsz * Edim));
            uint4* hd = (uint4*)hsb;
            for (int i = tid; i < 512; i += 256) hd[i] = hp[i];
        }
        __syncthreads();

        // 4 rows x 4 batches, 2 k per iteration via packed f32x2 FMA
        unsigned long long acc[16];
#pragma unroll
        for (int i = 0; i < 16; i++) acc[i] = 0ull;

#pragma unroll 4
        for (int kp = lane; kp < 512; kp += 32) {
            unsigned long long W0 = bf2f2(wp0[kp]);
            unsigned long long W1 = bf2f2(wp1[kp]);
            unsigned long long W2 = bf2f2(wp2[kp]);
            unsigned long long W3 = bf2f2(wp3[kp]);
            unsigned long long H0 = bf2f2(hsb[kp]);
            unsigned long long H1 = bf2f2(hsb[512 + kp]);
            unsigned long long H2 = bf2f2(hsb[1024 + kp]);
            unsigned long long H3 = bf2f2(hsb[1536 + kp]);
            fma2(acc[ 0], W0, H0); fma2(acc[ 1], W0, H1); fma2(acc[ 2], W0, H2); fma2(acc[ 3], W0, H3);
            fma2(acc[ 4], W1, H0); fma2(acc[ 5], W1, H1); fma2(acc[ 6], W1, H2); fma2(acc[ 7], W1, H3);
            fma2(acc[ 8], W2, H0); fma2(acc[ 9], W2, H1); fma2(acc[10], W2, H2); fma2(acc[11], W2, H3);
            fma2(acc[12], W3, H0); fma2(acc[13], W3, H1); fma2(acc[14], W3, H2); fma2(acc[15], W3, H3);
        }

        float a[16];
#pragma unroll
        for (int i = 0; i < 16; i++) a[i] = f2sum(acc[i]);
#pragma unroll
        for (int off = 16; off; off >>= 1)
#pragma unroll
            for (int i = 0; i < 16; i++)
                a[i] += __shfl_down_sync(~0u, a[i], off);

        if (lane == 0) {
#pragma unroll
            for (int rr = 0; rr < 4; rr++) {
                int r = r0 + rr, g = r >> 3, j = r & 7;
#pragma unroll
                for (int b = 0; b < 4; b++)
                    garr[(g * 4 + b) * 8 + j] = a[rr * 4 + b];
            }
        }
        __syncthreads();

        if (tid < 32) {
            int b = tid >> 3, j = tid & 7, e = e0 + j;
            const float* gb = gih + ((size_t)t * Bsz + b) * GDIM;
            float gi = garr[(0 * 4 + b) * 8 + j] + gb[e];
            float gf = garr[(1 * 4 + b) * 8 + j] + gb[Edim + e];
            float gG = garr[(2 * 4 + b) * 8 + j] + gb[2 * Edim + e];
            float go = garr[(3 * 4 + b) * 8 + j] + gb[3 * Edim + e];
            float c = sigm(gf) * cs[tid] + sigm(gi) * tanh_acc(gG);
            cs[tid] = c;
            float hv = sigm(go) * tanh_acc(c);
            hbf[(size_t)(t + 1) * (Bsz * Edim) + b * Edim + e] = __float2bfloat16(hv);
        }
        __syncthreads();

        if (tid == 0) grid_barrier_t0((unsigned int)(t + 1));
        __syncthreads();
    }
}

// ---------------- post-processing (in place on d_out) ----------------
__global__ void postprocess(float* __restrict__ out) {
    const int r = blockIdx.x;
    const int t_idx = r & (Tlen - 1);
    float* z = out + (size_t)r * Vdim;
    const int VV = Vdim - 1;
    const int tid = threadIdx.x;

    __shared__ float red[256];
    __shared__ float sh_shift, sh_eos;

    float mx = -3.402823466e38f;
    for (int v = tid; v < VV; v += 256) mx = fmaxf(mx, z[v]);
    red[tid] = mx; __syncthreads();
#pragma unroll
    for (int s = 128; s; s >>= 1) { if (tid < s) red[tid] = fmaxf(red[tid], red[tid + s]); __syncthreads(); }
    mx = red[0];
    __syncthreads();

    float sum = 0.f;
    for (int v = tid; v < VV; v += 256) sum += expf(z[v] - mx);
    red[tid] = sum; __syncthreads();
#pragma unroll
    for (int s = 128; s; s >>= 1) { if (tid < s) red[tid] += red[tid + s]; __syncthreads(); }

    if (tid == 0) {
        double lse = (double)mx + log((double)red[0]);
        double e   = (double)z[VV];
        double lsn = (-e < 0 ? -e : 0.0) - log1p(exp(-fabs(e)));
        double lsp = ( e < 0 ?  e : 0.0) - log1p(exp(-fabs(e)));
        double log_lb = (double)(t_idx + 1) * LOGB;
        double C1 = log_lb + lsn;
        double log_lb_eos = log(-expm1(log_lb)) + lsn;
        double d = log_lb_eos - lsp;
        double logsig_d = (d < 0 ? d : 0.0) - log1p(exp(-fabs(d)));
        double lpe = log_lb_eos - logsig_d;
        double m2 = fmax(C1, lpe);
        double Z  = m2 + log1p(exp(fmin(C1, lpe) - m2));
        sh_shift = (float)(C1 - lse - Z);
        sh_eos   = (float)(lpe - Z);
    }
    __syncthreads();

    float shift = sh_shift;
    for (int v = tid; v < VV; v += 256) z[v] += shift;
    if (tid == 0) z[VV] = sh_eos;
}

// ---------------- launcher ----------------
extern "C" void kernel_launch(void* const* d_in, const int* in_sizes, int n_in,
                              void* d_out, int out_size)
{
    (void)in_sizes; (void)n_in; (void)out_size;
    // 0:tokens 1:emb 2:Wproj 3:Wih0 4:Whh0 5:bih0 6:bhh0 7:Wih1 8:Whh1 9:bih1 10:bhh1
    const int*   tokens = (const int*)  d_in[0];
    const float* emb    = (const float*)d_in[1];
    const float* Wproj  = (const float*)d_in[2];
    const float* Wih0   = (const float*)d_in[3];
    const float* Whh0   = (const float*)d_in[4];
    const float* bih0   = (const float*)d_in[5];
    const float* bhh0   = (const float*)d_in[6];
    const float* Wih1   = (const float*)d_in[7];
    const float* Whh1   = (const float*)d_in[8];
    const float* bih1   = (const float*)d_in[9];
    const float* bhh1   = (const float*)d_in[10];
    float* out = (float*)d_out;

    __nv_bfloat16 *pxbf, *ph0bf, *ph1bf, *pw0, *pw1, *pwp;
    float *pg;
    cudaGetSymbolAddress((void**)&pxbf,  g_xbf);
    cudaGetSymbolAddress((void**)&pg,    g_gates);
    cudaGetSymbolAddress((void**)&ph0bf, g_h0bf);
    cudaGetSymbolAddress((void**)&ph1bf, g_h1bf);
    cudaGetSymbolAddress((void**)&pw0,   g_wih0bf);
    cudaGetSymbolAddress((void**)&pw1,   g_wih1bf);
    cudaGetSymbolAddress((void**)&pwp,   g_wprojbf);

    const int lstm_smem = (32 * 512 + 4 * 512) * 4 + (128 + 32) * 4;
    cudaFuncSetAttribute(lstm_layer, cudaFuncAttributeMaxDynamicSharedMemorySize, lstm_smem);

    // 0. weight conversions (fp32 -> bf16)
    f2bf_kernel<<<GDIM * Edim / 1024, 256>>>(Wih0, pw0, GDIM * Edim);
    f2bf_kernel<<<GDIM * Edim / 1024, 256>>>(Wih1, pw1, GDIM * Edim);
    f2bf_kernel<<<Vdim * (Edim / 1024), 256>>>(Wproj, pwp, Vdim * Edim);

    // 1. embedding (bf16 out)
    embed_kernel<<<(MROWS * Edim / 4 + 255) / 256, 256>>>(tokens, emb);

    // 2. layer-0 input gates (bf16 tensor cores)
    dim3 gg(MROWS / 128, GDIM / 128);
    gemm_bf16_nt<<<gg, 256>>>(pxbf, pw0, pg, MROWS, GDIM, Edim, bih0, bhh0, 0);

    // 3. layer-0 recurrence
    bar_reset<<<1, 1>>>();
    lstm_layer<<<NBLK, 256, lstm_smem>>>(pg, Whh0, ph0bf);

    // 4. layer-1 input gates
    gemm_bf16_nt<<<gg, 256>>>(ph0bf + Bsz * Edim, pw1, pg, MROWS, GDIM, Edim, bih1, bhh1, 0);

    // 5. layer-1 recurrence
    bar_reset<<<1, 1>>>();
    lstm_layer<<<NBLK, 256, lstm_smem>>>(pg, Whh1, ph1bf);

    // 6. projection -> d_out (rows remapped to [B,T])
    dim3 gp(MROWS / 128, Vdim / 128);
    gemm_bf16_nt<<<gp, 256>>>(ph1bf + Bsz * Edim, pwp, out, MROWS, Vdim, Edim,
                              nullptr, nullptr, 1);

    // 7. post-processing
    postprocess<<<MROWS, 256>>>(out);
}